// round 2
// baseline (speedup 1.0000x reference)
#include <cuda_runtime.h>
#include <cstdint>

#define NMAX   50000
#define EMAX   800000
#define FDIM   128
#define DDIM   32
#define CUT    5.0f
#define PI_F   3.14159265358979323846f

// ---------------- device scratch (static, allocation-free) ----------------
__device__ float  g_q [NMAX * DDIM];
__device__ float  g_q2[NMAX * DDIM];
__device__ int    g_cnt[NMAX];
__device__ int    g_off[NMAX];
__device__ int    g_cur[NMAX];
__device__ int    g_bsum[64];
__device__ float4 g_cwv[EMAX];

__device__ __forceinline__ float swish_f(float v) {
    return v / (1.0f + __expf(-v));
}

// ---------------- node transform: q = swish(swish(x@W1+b1)@W2+b2) ----------
// Simple, single-buffered, no aliasing tricks. 64 rows per block, 256 threads.
// smem: sW1 [128][128] | sX [64][132] (reused for h) | sW2 [128][32]
#define LDS   132
#define SW1_F (128 * 128)            // 16384
#define SX_F  (64 * LDS)             // 8448
#define SW2_F (128 * 32)             // 4096
#define SMEM_F (SW1_F + SX_F + SW2_F)  // 28928 floats = 115712 bytes

__global__ __launch_bounds__(256, 2) void transform_kernel(
    const float* __restrict__ x,
    const float* __restrict__ W1, const float* __restrict__ b1,
    const float* __restrict__ W2, const float* __restrict__ b2,
    int branch, int nrows)
{
    extern __shared__ float sm[];
    float* sW1 = sm;                 // [k][c] row-major, stride 128
    float* sX  = sm + SW1_F;         // [r][k] row-major, stride 132 (then h)
    float* sW2 = sm + SW1_F + SX_F;  // [k][c] row-major, stride 32
    float* q_out = branch ? g_q2 : g_q;

    const int tid  = threadIdx.x;
    const int row0 = blockIdx.x * 64;

    // ---- phase 0: load W1, W2, x-tile ----
    for (int i = tid; i < 4096; i += 256)
        *reinterpret_cast<float4*>(sW1 + 4 * i) =
            *reinterpret_cast<const float4*>(W1 + 4 * i);
    for (int i = tid; i < 1024; i += 256)
        *reinterpret_cast<float4*>(sW2 + 4 * i) =
            *reinterpret_cast<const float4*>(W2 + 4 * i);
    for (int i = tid; i < 2048; i += 256) {
        int r = i >> 5;              // 0..63
        int c = (i & 31) << 2;       // 0..124
        int row = row0 + r;
        float4 v = make_float4(0.f, 0.f, 0.f, 0.f);
        if (row < nrows)
            v = *reinterpret_cast<const float4*>(x + (size_t)row * 128 + c);
        *reinterpret_cast<float4*>(sX + r * LDS + c) = v;
    }
    __syncthreads();

    // ---- phase 1: h_pre = x @ W1 ; thread (ty,tx): rows ty*4.., cols tx*8..
    const int ty = tid >> 4;         // 0..15
    const int tx = tid & 15;         // 0..15
    float acc[4][8];
    #pragma unroll
    for (int i = 0; i < 4; i++)
        #pragma unroll
        for (int j = 0; j < 8; j++) acc[i][j] = 0.f;

    #pragma unroll 4
    for (int k = 0; k < 128; k++) {
        float a0 = sX[(ty * 4 + 0) * LDS + k];
        float a1 = sX[(ty * 4 + 1) * LDS + k];
        float a2 = sX[(ty * 4 + 2) * LDS + k];
        float a3 = sX[(ty * 4 + 3) * LDS + k];
        float w[8];
        reinterpret_cast<float4*>(w)[0] =
            *reinterpret_cast<const float4*>(sW1 + k * 128 + (tx << 3));
        reinterpret_cast<float4*>(w)[1] =
            *reinterpret_cast<const float4*>(sW1 + k * 128 + (tx << 3) + 4);
        #pragma unroll
        for (int j = 0; j < 8; j++) {
            acc[0][j] = fmaf(a0, w[j], acc[0][j]);
            acc[1][j] = fmaf(a1, w[j], acc[1][j]);
            acc[2][j] = fmaf(a2, w[j], acc[2][j]);
            acc[3][j] = fmaf(a3, w[j], acc[3][j]);
        }
    }
    __syncthreads();   // all reads of sX complete before overwrite

    // ---- phase 2: h = swish(h_pre + b1) -> overwrite sX ----
    #pragma unroll
    for (int j = 0; j < 8; j++) {
        float bj = __ldg(b1 + (tx << 3) + j);
        #pragma unroll
        for (int i = 0; i < 4; i++)
            sX[(ty * 4 + i) * LDS + (tx << 3) + j] = swish_f(acc[i][j] + bj);
    }
    __syncthreads();

    // ---- phase 3: q = swish(h @ W2 + b2) ; thread: row tid>>2, cols (tid&3)*8
    const int r2 = tid >> 2;         // 0..63
    const int c0 = (tid & 3) << 3;   // 0,8,16,24
    float acc2[8];
    #pragma unroll
    for (int j = 0; j < 8; j++) acc2[j] = 0.f;

    #pragma unroll 4
    for (int k = 0; k < 128; k++) {
        float a = sX[r2 * LDS + k];
        float w[8];
        reinterpret_cast<float4*>(w)[0] =
            *reinterpret_cast<const float4*>(sW2 + k * 32 + c0);
        reinterpret_cast<float4*>(w)[1] =
            *reinterpret_cast<const float4*>(sW2 + k * 32 + c0 + 4);
        #pragma unroll
        for (int j = 0; j < 8; j++) acc2[j] = fmaf(a, w[j], acc2[j]);
    }

    int row = row0 + r2;
    if (row < nrows) {
        float o[8];
        #pragma unroll
        for (int j = 0; j < 8; j++)
            o[j] = swish_f(acc2[j] + __ldg(b2 + c0 + j));
        float* qp = q_out + (size_t)row * DDIM + c0;
        *reinterpret_cast<float4*>(qp)     = reinterpret_cast<float4*>(o)[0];
        *reinterpret_cast<float4*>(qp + 4) = reinterpret_cast<float4*>(o)[1];
    }
}

// ---------------- CSR build ----------------
__global__ void zero_cnt_kernel(int n) {
    int i = blockIdx.x * blockDim.x + threadIdx.x;
    if (i < n) g_cnt[i] = 0;
}

__global__ void count_kernel(const int* __restrict__ dst,
                             const float* __restrict__ rij, int E) {
    int e = blockIdx.x * blockDim.x + threadIdx.x;
    if (e < E && rij[e] < CUT) atomicAdd(&g_cnt[dst[e]], 1);
}

// 2048 elems per block (256 thr x 8), 3-kernel exclusive scan
__global__ void scan1_kernel(int n) {
    __shared__ int s[256];
    int base = blockIdx.x * 2048 + threadIdx.x * 8;
    int v[8];
    int sum = 0;
    #pragma unroll
    for (int j = 0; j < 8; j++) {
        int idx = base + j;
        int t = (idx < n) ? g_cnt[idx] : 0;
        v[j] = sum;
        sum += t;
    }
    s[threadIdx.x] = sum;
    __syncthreads();
    for (int off = 1; off < 256; off <<= 1) {
        int t = (threadIdx.x >= off) ? s[threadIdx.x - off] : 0;
        __syncthreads();
        s[threadIdx.x] += t;
        __syncthreads();
    }
    int excl = s[threadIdx.x] - sum;
    if (threadIdx.x == 255) g_bsum[blockIdx.x] = s[255];
    #pragma unroll
    for (int j = 0; j < 8; j++) {
        int idx = base + j;
        if (idx < n) g_off[idx] = excl + v[j];
    }
}

__global__ void scan2_kernel(int nb) {
    if (threadIdx.x == 0) {
        int a = 0;
        for (int i = 0; i < nb; i++) { int t = g_bsum[i]; g_bsum[i] = a; a += t; }
    }
}

__global__ void scan3_kernel(int n) {
    int i = blockIdx.x * blockDim.x + threadIdx.x;
    if (i < n) {
        int o = g_off[i] + g_bsum[i >> 11];
        g_off[i] = o;
        g_cur[i] = o;
    }
}

__global__ void scatter_kernel(const int* __restrict__ src,
                               const int* __restrict__ dst,
                               const float* __restrict__ rij,
                               const float* __restrict__ vij, int E) {
    int e = blockIdx.x * blockDim.x + threadIdx.x;
    if (e >= E) return;
    float r = rij[e];
    if (r < CUT) {
        float c = 0.5f * (cosf(PI_F * r / CUT) + 1.0f);
        int p = atomicAdd(&g_cur[dst[e]], 1);
        g_cwv[p] = make_float4(c * vij[3 * e], c * vij[3 * e + 1],
                               c * vij[3 * e + 2], __int_as_float(src[e]));
    }
}

// ---------------- gather + cross + mix, one warp per node, lane = d --------
__global__ __launch_bounds__(256) void gather_kernel(
    const float* __restrict__ wmix, const float* __restrict__ bmix,
    float* __restrict__ out, int nNodes)
{
    int gw   = (blockIdx.x * 256 + threadIdx.x) >> 5;
    int lane = threadIdx.x & 31;
    if (gw >= nNodes) return;

    int start = g_off[gw];
    int m     = g_cnt[gw];

    float ax = 0.f, ay = 0.f, az = 0.f;
    float bx = 0.f, by = 0.f, bz = 0.f;

    int i = 0;
    for (; i + 2 <= m; i += 2) {
        float4 w0 = __ldg(&g_cwv[start + i]);
        float4 w1 = __ldg(&g_cwv[start + i + 1]);
        int s0 = __float_as_int(w0.w);
        int s1 = __float_as_int(w1.w);
        float qa = __ldg(&g_q [s0 * DDIM + lane]);
        float pa = __ldg(&g_q2[s0 * DDIM + lane]);
        float qb = __ldg(&g_q [s1 * DDIM + lane]);
        float pb = __ldg(&g_q2[s1 * DDIM + lane]);
        ax = fmaf(w0.x, qa, ax); ax = fmaf(w1.x, qb, ax);
        ay = fmaf(w0.y, qa, ay); ay = fmaf(w1.y, qb, ay);
        az = fmaf(w0.z, qa, az); az = fmaf(w1.z, qb, az);
        bx = fmaf(w0.x, pa, bx); bx = fmaf(w1.x, pb, bx);
        by = fmaf(w0.y, pa, by); by = fmaf(w1.y, pb, by);
        bz = fmaf(w0.z, pa, bz); bz = fmaf(w1.z, pb, bz);
    }
    if (i < m) {
        float4 w0 = __ldg(&g_cwv[start + i]);
        int s0 = __float_as_int(w0.w);
        float qa = __ldg(&g_q [s0 * DDIM + lane]);
        float pa = __ldg(&g_q2[s0 * DDIM + lane]);
        ax = fmaf(w0.x, qa, ax);
        ay = fmaf(w0.y, qa, ay);
        az = fmaf(w0.z, qa, az);
        bx = fmaf(w0.x, pa, bx);
        by = fmaf(w0.y, pa, by);
        bz = fmaf(w0.z, pa, bz);
    }

    float m0 = __ldg(wmix), m1 = __ldg(wmix + 1), m2 = __ldg(wmix + 2);
    float bm = __ldg(bmix);

    // cross(mu, mu2)
    float cx = ay * bz - az * by;
    float cy = az * bx - ax * bz;
    float cz = ax * by - ay * bx;

    size_t p = (size_t)gw * (DDIM * 3) + lane * 3;
    out[p + 0] = ax * m0 + bx * m1 + cx * m2 + bm;
    out[p + 1] = ay * m0 + by * m1 + cy * m2 + bm;
    out[p + 2] = az * m0 + bz * m1 + cz * m2 + bm;
}

// ---------------- launch ----------------
extern "C" void kernel_launch(void* const* d_in, const int* in_sizes, int n_in,
                              void* d_out, int out_size)
{
    const float* x    = (const float*)d_in[0];
    const float* rij  = (const float*)d_in[1];
    const float* vij  = (const float*)d_in[2];
    const int*   src  = (const int*)  d_in[3];
    const int*   dst  = (const int*)  d_in[4];
    const float* W1   = (const float*)d_in[5];
    const float* b1   = (const float*)d_in[6];
    const float* W2   = (const float*)d_in[7];
    const float* b2   = (const float*)d_in[8];
    const float* W1b  = (const float*)d_in[9];
    const float* b1b  = (const float*)d_in[10];
    const float* W2b  = (const float*)d_in[11];
    const float* b2b  = (const float*)d_in[12];
    const float* wmix = (const float*)d_in[13];
    const float* bmix = (const float*)d_in[14];
    float* out = (float*)d_out;

    int N = in_sizes[0] / FDIM;
    int E = in_sizes[1];
    if (N > NMAX) N = NMAX;
    if (E > EMAX) E = EMAX;

    const size_t smem_bytes = SMEM_F * sizeof(float);  // 115712
    cudaFuncSetAttribute(transform_kernel,
                         cudaFuncAttributeMaxDynamicSharedMemorySize,
                         (int)smem_bytes);

    int gT = (N + 63) / 64;
    transform_kernel<<<gT, 256, smem_bytes>>>(x, W1,  b1,  W2,  b2,  0, N);
    transform_kernel<<<gT, 256, smem_bytes>>>(x, W1b, b1b, W2b, b2b, 1, N);

    int gE = (E + 255) / 256;
    int gN = (N + 255) / 256;
    int nb = (N + 2047) / 2048;

    zero_cnt_kernel<<<gN, 256>>>(N);
    count_kernel<<<gE, 256>>>(dst, rij, E);
    scan1_kernel<<<nb, 256>>>(N);
    scan2_kernel<<<1, 32>>>(nb);
    scan3_kernel<<<gN, 256>>>(N);
    scatter_kernel<<<gE, 256>>>(src, dst, rij, vij, E);

    int gG = (N * 32 + 255) / 256;
    gather_kernel<<<gG, 256>>>(wmix, bmix, out, N);
}